// round 1
// baseline (speedup 1.0000x reference)
#include <cuda_runtime.h>

#define D_FEAT 64

// CSR row pointer scratch (N up to 100000 + 1). Device global: allocation-free.
__device__ int g_row_ptr[100001];

// Kernel A: row_ptr[r] = lower_bound(row, E, r) for r in [0, N]; row_ptr[N] = E.
__global__ void build_row_ptr(const int* __restrict__ row, int n, int E) {
    int r = blockIdx.x * blockDim.x + threadIdx.x;
    if (r > n) return;
    // lower bound: first index i with row[i] >= r
    int lo = 0, hi = E;
    while (lo < hi) {
        int mid = (lo + hi) >> 1;
        if (__ldg(&row[mid]) < r) lo = mid + 1;
        else hi = mid;
    }
    g_row_ptr[r] = lo;
}

// Kernel B: one warp per output row. Lane l owns features {2l, 2l+1} as float2.
// Edges of a row are contiguous (row is sorted), so no atomics needed.
__global__ void spmm_mean_warp_per_row(const float* __restrict__ x,
                                       const float* __restrict__ vals,
                                       const int* __restrict__ col,
                                       float* __restrict__ out,
                                       int n) {
    int warp_id = (blockIdx.x * blockDim.x + threadIdx.x) >> 5;
    int lane = threadIdx.x & 31;
    if (warp_id >= n) return;

    int s = g_row_ptr[warp_id];
    int e = g_row_ptr[warp_id + 1];

    float2 acc = make_float2(0.0f, 0.0f);

    int i = s;
    // Unroll by 4 to expose MLP>=4 on the x-gathers (hide L2 hit latency ~240cyc).
    for (; i + 4 <= e; i += 4) {
        int c0 = __ldg(&col[i + 0]);
        int c1 = __ldg(&col[i + 1]);
        int c2 = __ldg(&col[i + 2]);
        int c3 = __ldg(&col[i + 3]);
        float v0 = __ldg(&vals[i + 0]);
        float v1 = __ldg(&vals[i + 1]);
        float v2 = __ldg(&vals[i + 2]);
        float v3 = __ldg(&vals[i + 3]);
        float2 x0 = *reinterpret_cast<const float2*>(&x[(size_t)c0 * D_FEAT + 2 * lane]);
        float2 x1 = *reinterpret_cast<const float2*>(&x[(size_t)c1 * D_FEAT + 2 * lane]);
        float2 x2 = *reinterpret_cast<const float2*>(&x[(size_t)c2 * D_FEAT + 2 * lane]);
        float2 x3 = *reinterpret_cast<const float2*>(&x[(size_t)c3 * D_FEAT + 2 * lane]);
        acc.x = fmaf(v0, x0.x, acc.x); acc.y = fmaf(v0, x0.y, acc.y);
        acc.x = fmaf(v1, x1.x, acc.x); acc.y = fmaf(v1, x1.y, acc.y);
        acc.x = fmaf(v2, x2.x, acc.x); acc.y = fmaf(v2, x2.y, acc.y);
        acc.x = fmaf(v3, x3.x, acc.x); acc.y = fmaf(v3, x3.y, acc.y);
    }
    for (; i < e; i++) {
        int c = __ldg(&col[i]);
        float v = __ldg(&vals[i]);
        float2 xv = *reinterpret_cast<const float2*>(&x[(size_t)c * D_FEAT + 2 * lane]);
        acc.x = fmaf(v, xv.x, acc.x);
        acc.y = fmaf(v, xv.y, acc.y);
    }

    int deg = e - s;
    float inv = 1.0f / (float)(deg > 0 ? deg : 1);
    acc.x *= inv;
    acc.y *= inv;

    *reinterpret_cast<float2*>(&out[(size_t)warp_id * D_FEAT + 2 * lane]) = acc;
}

extern "C" void kernel_launch(void* const* d_in, const int* in_sizes, int n_in,
                              void* d_out, int out_size) {
    const float* x    = (const float*)d_in[0];
    const float* vals = (const float*)d_in[1];
    const int*   row  = (const int*)d_in[2];
    const int*   col  = (const int*)d_in[3];
    float* out = (float*)d_out;

    int n = in_sizes[0] / D_FEAT;   // 100000
    int E = in_sizes[1];            // 1200000

    // Kernel A: build CSR row pointers (n+1 entries)
    {
        int threads = 256;
        int blocks = (n + 1 + threads - 1) / threads;
        build_row_ptr<<<blocks, threads>>>(row, n, E);
    }

    // Kernel B: warp-per-row SpMM with mean
    {
        int threads = 256;                 // 8 warps -> 8 rows per block
        int rows_per_block = threads / 32;
        int blocks = (n + rows_per_block - 1) / rows_per_block;
        spmm_mean_warp_per_row<<<blocks, threads>>>(x, vals, col, out, n);
    }
}